// round 1
// baseline (speedup 1.0000x reference)
#include <cuda_runtime.h>
#include <cuda_bf16.h>
#include <math.h>

// Problem constants
#define NB   64          // batch N
#define CC   512         // C
#define CI_  256         // CI
#define HH   12
#define WW   4
#define HW   48          // H*W
#define PP   (NB*HW)     // 3072 pixels total
#define NM   12          // pooled positions
#define EPS_ 1e-5f

// ---------------- scratch (device globals; no allocation allowed) -------------
__device__ float g_xt   [PP * CC];    // x transposed to [p, c]
__device__ float g_theta[PP * CI_];   // [p, ci]
__device__ float g_phi  [PP * CI_];   // [p, ci]
__device__ float g_phip [NB * NM * CI_]; // [(i*12+m), ci]
__device__ float g_mpart[PP * 8];     // attention partial sums (8 i-groups)
__device__ float g_xln  [PP * CC];    // after LN1, [p, c]
__device__ float g_y1   [PP * CC];    // relu(conv1)
__device__ float g_r2   [PP * CC];    // xln + conv2(...)

// ---------------- transpose: x[N,C,H,W] -> xt[p=j*48+s, c] -------------------
__global__ __launch_bounds__(256) void transpose_kernel(const float* __restrict__ x,
                                                        float* __restrict__ xt) {
    int j  = blockIdx.x;
    int c0 = blockIdx.y * 128;
    __shared__ float t[128][49];
    int tid = threadIdx.x;
    const float* xb = x + j * (CC * HW);
    for (int idx = tid; idx < 128 * HW; idx += 256) {
        int cc = idx / HW, s = idx % HW;
        t[cc][s] = xb[(c0 + cc) * HW + s];
    }
    __syncthreads();
    float* ob = xt + j * HW * CC;
    for (int idx = tid; idx < HW * 128; idx += 256) {
        int s = idx >> 7, cc = idx & 127;
        ob[s * CC + c0 + cc] = t[cc][s];
    }
}

// ---------------- generic fp32 GEMM: C[m,n] = A[m,:]·B[n,:] (+bias)(relu)(+add)
// A: [M,K] row-major, B: [Nc,K] row-major. BM=BN=64, BK=32, 256 threads.
// All dims divisible by tiles for this problem (no bounds checks).
template<bool BIAS, bool RELU, bool ADD>
__global__ __launch_bounds__(256) void gemm_kernel(const float* __restrict__ A,
                                                   const float* __restrict__ B,
                                                   const float* __restrict__ bias,
                                                   const float* __restrict__ addsrc,
                                                   float* __restrict__ Cout,
                                                   int M, int Nc, int K) {
    __shared__ float As[64][33];
    __shared__ float Bs[64][33];
    int tid = threadIdx.x;
    int tx = tid & 15, ty = tid >> 4;
    int m0 = blockIdx.y * 64, n0 = blockIdx.x * 64;
    float acc[4][4] = {};
    for (int k0 = 0; k0 < K; k0 += 32) {
        #pragma unroll
        for (int l = 0; l < 8; l++) {
            int idx = tid + l * 256;
            int r = idx >> 5, kk = idx & 31;
            As[r][kk] = A[(m0 + r) * K + k0 + kk];
            Bs[r][kk] = B[(n0 + r) * K + k0 + kk];
        }
        __syncthreads();
        #pragma unroll
        for (int kk = 0; kk < 32; kk++) {
            float a[4], b[4];
            #pragma unroll
            for (int i = 0; i < 4; i++) a[i] = As[ty + 16 * i][kk];   // broadcast
            #pragma unroll
            for (int jj = 0; jj < 4; jj++) b[jj] = Bs[tx + 16 * jj][kk]; // conflict-free
            #pragma unroll
            for (int i = 0; i < 4; i++)
                #pragma unroll
                for (int jj = 0; jj < 4; jj++)
                    acc[i][jj] += a[i] * b[jj];
        }
        __syncthreads();
    }
    #pragma unroll
    for (int i = 0; i < 4; i++) {
        int row = m0 + ty + 16 * i;
        #pragma unroll
        for (int jj = 0; jj < 4; jj++) {
            int col = n0 + tx + 16 * jj;
            float v = acc[i][jj];
            if (BIAS) v += bias[col];
            if (RELU) v = fmaxf(v, 0.f);
            if (ADD)  v += addsrc[row * Nc + col];
            Cout[row * Nc + col] = v;
        }
    }
}

// ---------------- maxpool 2x2 on phi -> phip[(i*12+m), ci] -------------------
__global__ __launch_bounds__(256) void pool_kernel(const float* __restrict__ phi,
                                                   float* __restrict__ phip) {
    int i = blockIdx.x;
    int c = threadIdx.x;   // 256 = CI
    #pragma unroll
    for (int m = 0; m < NM; m++) {
        int ph = m >> 1, pw = m & 1;
        float v = -1e30f;
        #pragma unroll
        for (int dh = 0; dh < 2; dh++)
            #pragma unroll
            for (int dw = 0; dw < 2; dw++) {
                int s = (2 * ph + dh) * WW + (2 * pw + dw);
                v = fmaxf(v, phi[(i * HW + s) * CI_ + c]);
            }
        phip[(i * NM + m) * CI_ + c] = v;
    }
}

// ---------------- attention: F = theta @ phip^T, group-max over m, sum over i -
// One block per (j, igroup of 8 i's). Rows 48, cols 96, K=256.
__global__ __launch_bounds__(256) void attn_kernel(const float* __restrict__ theta,
                                                   const float* __restrict__ phip,
                                                   float* __restrict__ mpart) {
    int j  = blockIdx.x;
    int ig = blockIdx.y;
    __shared__ float As[48][33];
    __shared__ float Bs[96][33];
    __shared__ float Fs[48][97];
    __shared__ float Gm[48][8];
    int tid = threadIdx.x;
    int tx = tid & 15, ty = tid >> 4;
    float acc[3][6] = {};
    for (int k0 = 0; k0 < CI_; k0 += 32) {
        #pragma unroll
        for (int l = 0; l < 6; l++) {
            int idx = tid + l * 256;
            int r = idx >> 5, kk = idx & 31;
            As[r][kk] = theta[(j * HW + r) * CI_ + k0 + kk];
        }
        #pragma unroll
        for (int l = 0; l < 12; l++) {
            int idx = tid + l * 256;
            int r = idx >> 5, kk = idx & 31;
            Bs[r][kk] = phip[(ig * 96 + r) * CI_ + k0 + kk];
        }
        __syncthreads();
        #pragma unroll
        for (int kk = 0; kk < 32; kk++) {
            float a[3], b[6];
            #pragma unroll
            for (int i = 0; i < 3; i++) a[i] = As[ty + 16 * i][kk];
            #pragma unroll
            for (int jj = 0; jj < 6; jj++) b[jj] = Bs[tx + 16 * jj][kk];
            #pragma unroll
            for (int i = 0; i < 3; i++)
                #pragma unroll
                for (int jj = 0; jj < 6; jj++)
                    acc[i][jj] += a[i] * b[jj];
        }
        __syncthreads();
    }
    #pragma unroll
    for (int i = 0; i < 3; i++)
        #pragma unroll
        for (int jj = 0; jj < 6; jj++)
            Fs[ty + 16 * i][tx + 16 * jj] = acc[i][jj];
    __syncthreads();
    // per-row, per-i (12 cols each) max
    for (int t = tid; t < 48 * 8; t += 256) {
        int row = t % 48, g = t / 48;
        float v = Fs[row][g * NM];
        #pragma unroll
        for (int m = 1; m < NM; m++) v = fmaxf(v, Fs[row][g * NM + m]);
        Gm[row][g] = v;
    }
    __syncthreads();
    if (tid < 48) {
        float s = 0.f;
        #pragma unroll
        for (int g = 0; g < 8; g++) s += Gm[tid][g];
        mpart[(j * HW + tid) * 8 + ig] = s * (1.0f / 12.0f);
    }
}

// ---------------- block reduction helper --------------------------------------
__device__ __forceinline__ float blockReduceSum256(float v, float* sbuf) {
    #pragma unroll
    for (int o = 16; o > 0; o >>= 1) v += __shfl_down_sync(0xffffffffu, v, o);
    int lane = threadIdx.x & 31, w = threadIdx.x >> 5;
    if (lane == 0) sbuf[w] = v;
    __syncthreads();
    v = (threadIdx.x < 8) ? sbuf[threadIdx.x] : 0.f;
    if (w == 0) {
        #pragma unroll
        for (int o = 4; o > 0; o >>= 1) v += __shfl_down_sync(0xffu, v, o);
    }
    return v; // valid in thread 0
}

// ---------------- res1 + LN1: xln = LN(x*(1+M)) -------------------------------
__global__ __launch_bounds__(256) void ln1_kernel(const float* __restrict__ xt,
                                                  const float* __restrict__ mpart,
                                                  const float* __restrict__ gam,
                                                  const float* __restrict__ bet,
                                                  float* __restrict__ xln) {
    int j = blockIdx.x, tid = threadIdx.x;
    __shared__ float sbuf[32];
    __shared__ float s_mu, s_rstd;
    __shared__ float s_scale[HW];
    if (tid < HW) {
        float a = 0.f;
        #pragma unroll
        for (int g = 0; g < 8; g++) a += mpart[(j * HW + tid) * 8 + g];
        s_scale[tid] = 1.0f + a;
    }
    __syncthreads();
    const float* base = xt + j * (HW * CC);
    float sum = 0.f, sq = 0.f;
    for (int idx = tid; idx < HW * CC; idx += 256) {
        float v = base[idx] * s_scale[idx >> 9];
        sum += v; sq += v * v;
    }
    float ts = blockReduceSum256(sum, sbuf);
    __syncthreads();
    float tq = blockReduceSum256(sq, sbuf);
    if (tid == 0) {
        float mu = ts * (1.0f / (HW * CC));
        float var = tq * (1.0f / (HW * CC)) - mu * mu;
        s_mu = mu; s_rstd = rsqrtf(var + EPS_);
    }
    __syncthreads();
    float mu = s_mu, rstd = s_rstd;
    float* o = xln + j * (HW * CC);
    for (int idx = tid; idx < HW * CC; idx += 256) {
        int s = idx >> 9, c = idx & 511;
        float v = base[idx] * s_scale[s];
        o[idx] = (v - mu) * rstd * gam[c * HW + s] + bet[c * HW + s];
    }
}

// ---------------- LN2 + output in NCHW layout ---------------------------------
__global__ __launch_bounds__(256) void ln2_kernel(const float* __restrict__ r2,
                                                  const float* __restrict__ gam,
                                                  const float* __restrict__ bet,
                                                  float* __restrict__ out) {
    int j = blockIdx.x, tid = threadIdx.x;
    __shared__ float sbuf[32];
    __shared__ float s_mu, s_rstd;
    const float* base = r2 + j * (HW * CC);
    float sum = 0.f, sq = 0.f;
    for (int idx = tid; idx < HW * CC; idx += 256) {
        float v = base[idx];
        sum += v; sq += v * v;
    }
    float ts = blockReduceSum256(sum, sbuf);
    __syncthreads();
    float tq = blockReduceSum256(sq, sbuf);
    if (tid == 0) {
        float mu = ts * (1.0f / (HW * CC));
        float var = tq * (1.0f / (HW * CC)) - mu * mu;
        s_mu = mu; s_rstd = rsqrtf(var + EPS_);
    }
    __syncthreads();
    float mu = s_mu, rstd = s_rstd;
    float* o = out + j * (HW * CC);
    for (int idx = tid; idx < HW * CC; idx += 256) {
        // idx = c*48 + sp  (coalesced output write)
        int c = idx / HW, sp = idx % HW;
        float v = base[sp * CC + c];
        o[idx] = (v - mu) * rstd * gam[idx] + bet[idx];
    }
}

// ---------------- launcher ----------------------------------------------------
extern "C" void kernel_launch(void* const* d_in, const int* in_sizes, int n_in,
                              void* d_out, int out_size) {
    const float* x       = (const float*)d_in[0];
    const float* theta_w = (const float*)d_in[1];
    const float* theta_b = (const float*)d_in[2];
    const float* phi_w   = (const float*)d_in[3];
    const float* phi_b   = (const float*)d_in[4];
    const float* conv1_w = (const float*)d_in[5];
    const float* conv2_w = (const float*)d_in[6];
    const float* ln1_g   = (const float*)d_in[7];
    const float* ln1_b   = (const float*)d_in[8];
    const float* ln2_g   = (const float*)d_in[9];
    const float* ln2_b   = (const float*)d_in[10];
    float* out = (float*)d_out;

    float *xt, *theta, *phi, *phip, *mpart, *xln, *y1, *r2;
    cudaGetSymbolAddress((void**)&xt,    g_xt);
    cudaGetSymbolAddress((void**)&theta, g_theta);
    cudaGetSymbolAddress((void**)&phi,   g_phi);
    cudaGetSymbolAddress((void**)&phip,  g_phip);
    cudaGetSymbolAddress((void**)&mpart, g_mpart);
    cudaGetSymbolAddress((void**)&xln,   g_xln);
    cudaGetSymbolAddress((void**)&y1,    g_y1);
    cudaGetSymbolAddress((void**)&r2,    g_r2);

    transpose_kernel<<<dim3(NB, 4), 256>>>(x, xt);
    // theta / phi projections: [3072,512] @ [256,512]^T
    gemm_kernel<true, false, false><<<dim3(CI_ / 64, PP / 64), 256>>>(
        xt, theta_w, theta_b, nullptr, theta, PP, CI_, CC);
    gemm_kernel<true, false, false><<<dim3(CI_ / 64, PP / 64), 256>>>(
        xt, phi_w, phi_b, nullptr, phi, PP, CI_, CC);
    pool_kernel<<<NB, 256>>>(phi, phip);
    attn_kernel<<<dim3(NB, 8), 256>>>(theta, phip, mpart);
    ln1_kernel<<<NB, 256>>>(xt, mpart, ln1_g, ln1_b, xln);
    // conv1 + relu: [3072,512] @ [512,512]^T
    gemm_kernel<false, true, false><<<dim3(CC / 64, PP / 64), 256>>>(
        xln, conv1_w, nullptr, nullptr, y1, PP, CC, CC);
    // conv2 + residual add
    gemm_kernel<false, false, true><<<dim3(CC / 64, PP / 64), 256>>>(
        y1, conv2_w, nullptr, xln, r2, PP, CC, CC);
    ln2_kernel<<<NB, 256>>>(r2, ln2_g, ln2_b, out);
}

// round 2
// speedup vs baseline: 1.0388x; 1.0388x over previous
#include <cuda_runtime.h>
#include <cuda_bf16.h>
#include <math.h>

// Problem constants
#define NB   64          // batch N
#define CC   512         // C
#define CI_  256         // CI
#define HH   12
#define WW   4
#define HW   48          // H*W
#define PP   (NB*HW)     // 3072 pixels total
#define NM   12          // pooled positions
#define NCF  (NB*NM)     // 768 attention columns
#define EPS_ 1e-5f

// ---------------- scratch (device globals; no allocation allowed) -------------
__device__ float g_xt   [PP * CC];    // x transposed to [p, c]
__device__ float g_theta[PP * CI_];   // [p, ci]
__device__ float g_phi  [PP * CI_];   // [p, ci]
__device__ float g_phip [NCF * CI_];  // [(i*12+m), ci]
__device__ float g_F    [PP * NCF];   // attention logits
__device__ float g_M    [PP];         // per-pixel attention scale
__device__ float g_xln  [PP * CC];    // after LN1, [p, c]
__device__ float g_y1   [PP * CC];    // relu(conv1)
__device__ float g_r2   [PP * CC];    // xln + conv2(...)

// ---------------- f32x2 packed FMA helpers ------------------------------------
__device__ __forceinline__ void ffma2(unsigned long long& d,
                                      unsigned long long a,
                                      unsigned long long b) {
    asm("fma.rn.f32x2 %0, %1, %2, %0;" : "+l"(d) : "l"(a), "l"(b));
}
__device__ __forceinline__ unsigned long long dup2(float v) {
    unsigned u = __float_as_uint(v);
    return (unsigned long long)u | ((unsigned long long)u << 32);
}
__device__ __forceinline__ float2 unpack2(unsigned long long u) {
    float2 r;
    r.x = __uint_as_float((unsigned)u);
    r.y = __uint_as_float((unsigned)(u >> 32));
    return r;
}

// ---------------- transpose: x[N,C,H,W] -> xt[p=j*48+s, c] -------------------
__global__ __launch_bounds__(256) void transpose_kernel(const float* __restrict__ x,
                                                        float* __restrict__ xt) {
    int j  = blockIdx.x;
    int c0 = blockIdx.y * 128;
    __shared__ float t[128][49];
    int tid = threadIdx.x;
    const float* xb = x + j * (CC * HW);
    for (int idx = tid; idx < 128 * HW; idx += 256) {
        int cc = idx / HW, s = idx % HW;
        t[cc][s] = xb[(c0 + cc) * HW + s];
    }
    __syncthreads();
    float* ob = xt + j * HW * CC;
    for (int idx = tid; idx < HW * 128; idx += 256) {
        int s = idx >> 7, cc = idx & 127;
        ob[s * CC + c0 + cc] = t[cc][s];
    }
}

// ---------------- fast fp32x2 GEMM core ---------------------------------------
// C[m,n] = A[m,:]·B[n,:] (+bias)(relu)(+add).  A:[M,K], B:[Nc,K] row-major.
// BM=128, BN=64, BK=16, 256 threads, 8x4 per thread, inner loop pure FFMA2.
#define AS_STRIDE 268   // floats per k-row of As2 (256 data + pad; 16B-aligned, 2-way STS)
#define BS_STRIDE 68

template<bool BIAS, bool RELU, bool ADD>
__device__ __forceinline__ void gemm2_body(const float* __restrict__ A,
                                           const float* __restrict__ B,
                                           const float* __restrict__ bias,
                                           const float* __restrict__ addsrc,
                                           float* __restrict__ C,
                                           int Nc, int K, int m0, int n0) {
    __shared__ float As2[16 * AS_STRIDE];
    __shared__ float Bs [16 * BS_STRIDE];
    int tid = threadIdx.x;
    int tx = tid & 15, ty = tid >> 4;
    int rowA = tid >> 2;                 // 0..63
    int kq   = (tid & 3) * 4;            // 0,4,8,12

    const float* Ap0 = A + (m0 + rowA) * K + kq;
    const float* Ap1 = Ap0 + 64 * K;
    const float* Bp  = B + (n0 + rowA) * K + kq;

    unsigned long long acc[8][2];
    #pragma unroll
    for (int i = 0; i < 8; i++) { acc[i][0] = 0ull; acc[i][1] = 0ull; }

    float4 va0 = *(const float4*)Ap0;
    float4 va1 = *(const float4*)Ap1;
    float4 vb  = *(const float4*)Bp;

    int nch = K >> 4;
    for (int ch = 0; ch < nch; ch++) {
        // stage into shared (A pre-duplicated for f32x2 broadcast)
        {
            float a0[4] = {va0.x, va0.y, va0.z, va0.w};
            float a1[4] = {va1.x, va1.y, va1.z, va1.w};
            float b4[4] = {vb.x,  vb.y,  vb.z,  vb.w};
            #pragma unroll
            for (int t = 0; t < 4; t++) {
                *(unsigned long long*)&As2[(kq + t) * AS_STRIDE + 2 * rowA]       = dup2(a0[t]);
                *(unsigned long long*)&As2[(kq + t) * AS_STRIDE + 2 * rowA + 128] = dup2(a1[t]);
                Bs[(kq + t) * BS_STRIDE + rowA] = b4[t];
            }
        }
        __syncthreads();
        if (ch + 1 < nch) {
            va0 = *(const float4*)(Ap0 + (ch + 1) * 16);
            va1 = *(const float4*)(Ap1 + (ch + 1) * 16);
            vb  = *(const float4*)(Bp  + (ch + 1) * 16);
        }
        #pragma unroll
        for (int kk = 0; kk < 16; kk++) {
            const float* ap = As2 + kk * AS_STRIDE + 8 * ty;
            ulonglong2 aA = *(const ulonglong2*)(ap);        // rows ty*4+0,1 (dup'd)
            ulonglong2 aB = *(const ulonglong2*)(ap + 4);    // rows ty*4+2,3
            ulonglong2 aC = *(const ulonglong2*)(ap + 128);  // rows 64+ty*4+0,1
            ulonglong2 aD = *(const ulonglong2*)(ap + 132);  // rows 64+ty*4+2,3
            ulonglong2 bb = *(const ulonglong2*)(Bs + kk * BS_STRIDE + 4 * tx);
            ffma2(acc[0][0], aA.x, bb.x); ffma2(acc[0][1], aA.x, bb.y);
            ffma2(acc[1][0], aA.y, bb.x); ffma2(acc[1][1], aA.y, bb.y);
            ffma2(acc[2][0], aB.x, bb.x); ffma2(acc[2][1], aB.x, bb.y);
            ffma2(acc[3][0], aB.y, bb.x); ffma2(acc[3][1], aB.y, bb.y);
            ffma2(acc[4][0], aC.x, bb.x); ffma2(acc[4][1], aC.x, bb.y);
            ffma2(acc[5][0], aC.y, bb.x); ffma2(acc[5][1], aC.y, bb.y);
            ffma2(acc[6][0], aD.x, bb.x); ffma2(acc[6][1], aD.x, bb.y);
            ffma2(acc[7][0], aD.y, bb.x); ffma2(acc[7][1], aD.y, bb.y);
        }
        __syncthreads();
    }
    // epilogue
    int col = n0 + tx * 4;
    float4 bsv = make_float4(0.f, 0.f, 0.f, 0.f);
    if (BIAS) bsv = *(const float4*)&bias[col];
    #pragma unroll
    for (int i = 0; i < 8; i++) {
        int row = m0 + ((i < 4) ? (ty * 4 + i) : (64 + ty * 4 + (i - 4)));
        float2 lo = unpack2(acc[i][0]);
        float2 hi = unpack2(acc[i][1]);
        float4 v = make_float4(lo.x, lo.y, hi.x, hi.y);
        if (BIAS) { v.x += bsv.x; v.y += bsv.y; v.z += bsv.z; v.w += bsv.w; }
        if (RELU) {
            v.x = fmaxf(v.x, 0.f); v.y = fmaxf(v.y, 0.f);
            v.z = fmaxf(v.z, 0.f); v.w = fmaxf(v.w, 0.f);
        }
        if (ADD) {
            float4 ad = *(const float4*)&addsrc[row * Nc + col];
            v.x += ad.x; v.y += ad.y; v.z += ad.z; v.w += ad.w;
        }
        *(float4*)&C[row * Nc + col] = v;
    }
}

template<bool BIAS, bool RELU, bool ADD>
__global__ __launch_bounds__(256, 2) void gemm2_kernel(const float* __restrict__ A,
                                                       const float* __restrict__ B,
                                                       const float* __restrict__ bias,
                                                       const float* __restrict__ addsrc,
                                                       float* __restrict__ C,
                                                       int Nc, int K) {
    gemm2_body<BIAS, RELU, ADD>(A, B, bias, addsrc, C, Nc, K,
                                blockIdx.y * 128, blockIdx.x * 64);
}

// dual projection: z=0 -> theta, z=1 -> phi (fills the chip in one launch)
__global__ __launch_bounds__(256, 2) void gemm2_dual_kernel(const float* __restrict__ A,
                                                            const float* __restrict__ B0,
                                                            const float* __restrict__ B1,
                                                            const float* __restrict__ bias0,
                                                            const float* __restrict__ bias1,
                                                            float* __restrict__ C0,
                                                            float* __restrict__ C1,
                                                            int Nc, int K) {
    bool z = blockIdx.z != 0;
    gemm2_body<true, false, false>(A, z ? B1 : B0, z ? bias1 : bias0, nullptr,
                                   z ? C1 : C0, Nc, K,
                                   blockIdx.y * 128, blockIdx.x * 64);
}

// ---------------- maxpool 2x2 on phi -> phip[(i*12+m), ci] -------------------
__global__ __launch_bounds__(256) void pool_kernel(const float* __restrict__ phi,
                                                   float* __restrict__ phip) {
    int i = blockIdx.x;
    int c = threadIdx.x;   // 256 = CI
    #pragma unroll
    for (int m = 0; m < NM; m++) {
        int ph = m >> 1, pw = m & 1;
        float v = -1e30f;
        #pragma unroll
        for (int dh = 0; dh < 2; dh++)
            #pragma unroll
            for (int dw = 0; dw < 2; dw++) {
                int s = (2 * ph + dh) * WW + (2 * pw + dw);
                v = fmaxf(v, phi[(i * HW + s) * CI_ + c]);
            }
        phip[(i * NM + m) * CI_ + c] = v;
    }
}

// ---------------- reduce F -> M: M[p] = (1/12) sum_i max_m F[p][i*12+m] ------
__global__ __launch_bounds__(256) void reduceM_kernel(const float* __restrict__ F,
                                                      float* __restrict__ Mv) {
    int p = blockIdx.x * 8 + (threadIdx.x >> 5);
    int lane = threadIdx.x & 31;
    const float* row = F + p * NCF;
    float s = 0.f;
    #pragma unroll
    for (int g = lane; g < NB; g += 32) {
        float v = row[g * NM];
        #pragma unroll
        for (int m = 1; m < NM; m++) v = fmaxf(v, row[g * NM + m]);
        s += v;
    }
    #pragma unroll
    for (int o = 16; o > 0; o >>= 1) s += __shfl_down_sync(0xffffffffu, s, o);
    if (lane == 0) Mv[p] = s * (1.0f / 12.0f);
}

// ---------------- block reduction helper --------------------------------------
__device__ __forceinline__ float blockReduceSum256(float v, float* sbuf) {
    #pragma unroll
    for (int o = 16; o > 0; o >>= 1) v += __shfl_down_sync(0xffffffffu, v, o);
    int lane = threadIdx.x & 31, w = threadIdx.x >> 5;
    if (lane == 0) sbuf[w] = v;
    __syncthreads();
    v = (threadIdx.x < 8) ? sbuf[threadIdx.x] : 0.f;
    if (w == 0) {
        #pragma unroll
        for (int o = 4; o > 0; o >>= 1) v += __shfl_down_sync(0xffu, v, o);
    }
    return v; // valid in thread 0
}

// ---------------- res1 + LN1: xln = LN(x*(1+M)) -------------------------------
__global__ __launch_bounds__(256) void ln1_kernel(const float* __restrict__ xt,
                                                  const float* __restrict__ Mv,
                                                  const float* __restrict__ gam,
                                                  const float* __restrict__ bet,
                                                  float* __restrict__ xln) {
    int j = blockIdx.x, tid = threadIdx.x;
    __shared__ float sbuf[32];
    __shared__ float s_mu, s_rstd;
    __shared__ float s_scale[HW];
    if (tid < HW) s_scale[tid] = 1.0f + Mv[j * HW + tid];
    __syncthreads();
    const float* base = xt + j * (HW * CC);
    float sum = 0.f, sq = 0.f;
    for (int idx = tid; idx < HW * CC; idx += 256) {
        float v = base[idx] * s_scale[idx >> 9];
        sum += v; sq += v * v;
    }
    float ts = blockReduceSum256(sum, sbuf);
    __syncthreads();
    float tq = blockReduceSum256(sq, sbuf);
    if (tid == 0) {
        float mu = ts * (1.0f / (HW * CC));
        float var = tq * (1.0f / (HW * CC)) - mu * mu;
        s_mu = mu; s_rstd = rsqrtf(var + EPS_);
    }
    __syncthreads();
    float mu = s_mu, rstd = s_rstd;
    float* o = xln + j * (HW * CC);
    for (int idx = tid; idx < HW * CC; idx += 256) {
        int s = idx >> 9, c = idx & 511;
        float v = base[idx] * s_scale[s];
        o[idx] = (v - mu) * rstd * gam[c * HW + s] + bet[c * HW + s];
    }
}

// ---------------- LN2 + output in NCHW layout ---------------------------------
__global__ __launch_bounds__(256) void ln2_kernel(const float* __restrict__ r2,
                                                  const float* __restrict__ gam,
                                                  const float* __restrict__ bet,
                                                  float* __restrict__ out) {
    int j = blockIdx.x, tid = threadIdx.x;
    __shared__ float sbuf[32];
    __shared__ float s_mu, s_rstd;
    const float* base = r2 + j * (HW * CC);
    float sum = 0.f, sq = 0.f;
    for (int idx = tid; idx < HW * CC; idx += 256) {
        float v = base[idx];
        sum += v; sq += v * v;
    }
    float ts = blockReduceSum256(sum, sbuf);
    __syncthreads();
    float tq = blockReduceSum256(sq, sbuf);
    if (tid == 0) {
        float mu = ts * (1.0f / (HW * CC));
        float var = tq * (1.0f / (HW * CC)) - mu * mu;
        s_mu = mu; s_rstd = rsqrtf(var + EPS_);
    }
    __syncthreads();
    float mu = s_mu, rstd = s_rstd;
    float* o = out + j * (HW * CC);
    for (int idx = tid; idx < HW * CC; idx += 256) {
        int c = idx / HW, sp = idx % HW;
        float v = base[sp * CC + c];
        o[idx] = (v - mu) * rstd * gam[idx] + bet[idx];
    }
}

// ---------------- launcher ----------------------------------------------------
extern "C" void kernel_launch(void* const* d_in, const int* in_sizes, int n_in,
                              void* d_out, int out_size) {
    const float* x       = (const float*)d_in[0];
    const float* theta_w = (const float*)d_in[1];
    const float* theta_b = (const float*)d_in[2];
    const float* phi_w   = (const float*)d_in[3];
    const float* phi_b   = (const float*)d_in[4];
    const float* conv1_w = (const float*)d_in[5];
    const float* conv2_w = (const float*)d_in[6];
    const float* ln1_g   = (const float*)d_in[7];
    const float* ln1_b   = (const float*)d_in[8];
    const float* ln2_g   = (const float*)d_in[9];
    const float* ln2_b   = (const float*)d_in[10];
    float* out = (float*)d_out;

    float *xt, *theta, *phi, *phip, *F, *Mv, *xln, *y1, *r2;
    cudaGetSymbolAddress((void**)&xt,    g_xt);
    cudaGetSymbolAddress((void**)&theta, g_theta);
    cudaGetSymbolAddress((void**)&phi,   g_phi);
    cudaGetSymbolAddress((void**)&phip,  g_phip);
    cudaGetSymbolAddress((void**)&F,     g_F);
    cudaGetSymbolAddress((void**)&Mv,    g_M);
    cudaGetSymbolAddress((void**)&xln,   g_xln);
    cudaGetSymbolAddress((void**)&y1,    g_y1);
    cudaGetSymbolAddress((void**)&r2,    g_r2);

    transpose_kernel<<<dim3(NB, 4), 256>>>(x, xt);
    // theta & phi projections in one launch: [3072,512] @ [256,512]^T
    gemm2_dual_kernel<<<dim3(CI_ / 64, PP / 128, 2), 256>>>(
        xt, theta_w, phi_w, theta_b, phi_b, theta, phi, CI_, CC);
    pool_kernel<<<NB, 256>>>(phi, phip);
    // attention logits: [3072,256] @ [768,256]^T
    gemm2_kernel<false, false, false><<<dim3(NCF / 64, PP / 128), 256>>>(
        theta, phip, nullptr, nullptr, F, NCF, CI_);
    reduceM_kernel<<<PP / 8, 256>>>(F, Mv);
    ln1_kernel<<<NB, 256>>>(xt, Mv, ln1_g, ln1_b, xln);
    // conv1 + relu: [3072,512] @ [512,512]^T
    gemm2_kernel<false, true, false><<<dim3(CC / 64, PP / 128), 256>>>(
        xln, conv1_w, nullptr, nullptr, y1, CC, CC);
    // conv2 + residual add
    gemm2_kernel<false, false, true><<<dim3(CC / 64, PP / 128), 256>>>(
        y1, conv2_w, nullptr, xln, r2, CC, CC);
    ln2_kernel<<<NB, 256>>>(r2, ln2_g, ln2_b, out);
}